// round 5
// baseline (speedup 1.0000x reference)
#include <cuda_runtime.h>
#include <cuda_bf16.h>
#include <cuda_fp16.h>
#include <cstdint>

#define N_NODES 100000
#define N_EDGES 1600000
#define IN_F    4
#define HDIM    128
#define R_ROB   20
#define OUT_F   2

#define SCAN_B      1024
#define NSCAN_BLKS  ((N_NODES + SCAN_B - 1) / SCAN_B)   // 98

// ---------------- scratch (device globals; no allocation allowed) ----------
__device__ __half2 g_hh [(size_t)N_NODES * HDIM / 2];  // fp16 feature buffer
__device__ float   g_agg[(size_t)N_NODES * HDIM];      // aggregation result (fp32)
__device__ float   g_wp [64 * 256];                     // W2 pre-packed in k-pairs
__device__ float   g_dinv[N_NODES];
__device__ float   g_sums[HDIM];
__device__ int     g_insize;

__device__ int g_cnt   [N_NODES];
__device__ int g_excl  [N_NODES];
__device__ int g_rowptr[N_NODES];
__device__ int g_cursor[N_NODES];
__device__ int g_bsum  [NSCAN_BLKS];
__device__ int g_boff  [NSCAN_BLKS];
__device__ int g_esrc  [N_EDGES];

// packed f32x2 fma: {d.lo,d.hi} = {a.lo*b.lo+c.lo, a.hi*b.hi+c.hi}
__device__ __forceinline__ void fma2(unsigned long long& acc,
                                     unsigned long long a, unsigned long long b) {
    asm("fma.rn.f32x2 %0, %1, %2, %3;" : "=l"(acc) : "l"(a), "l"(b), "l"(acc));
}
__device__ __forceinline__ unsigned long long ld_u64(const void* p) {
    return *reinterpret_cast<const unsigned long long*>(p);
}

// ---------------- K0: init ----------------
__global__ void k_init() {
    int i = blockIdx.x * blockDim.x + threadIdx.x;
    if (i < N_NODES) g_cnt[i] = 0;
    if (i < HDIM)    g_sums[i] = 0.0f;
    if (i == 0)      g_insize = 0;
}

// ---------------- K0b: pre-pack W2 into k-pair-interleaved layout ----------
// g_wp[kk*256 + j*2 + 0] = W2[2kk  ][j];  g_wp[kk*256 + j*2 + 1] = W2[2kk+1][j]
__global__ void k_prepW(const float* __restrict__ W2) {
    int idx = blockIdx.x * blockDim.x + threadIdx.x;   // 0..8191
    if (idx >= 64 * 128) return;
    int kk = idx >> 7, j = idx & 127;
    g_wp[kk*256 + j*2]     = W2[(2*kk)    * HDIM + j];
    g_wp[kk*256 + j*2 + 1] = W2[(2*kk+1)  * HDIM + j];
}

// ---------------- K1: count in-degree ----------------
__global__ void k_count(const int* __restrict__ dst) {
    int e = blockIdx.x * blockDim.x + threadIdx.x;
    if (e < N_EDGES) atomicAdd(&g_cnt[dst[e]], 1);
}

// ---------------- K2a: per-block inclusive scan ----------------
__global__ void k_scan1() {
    __shared__ int sm[SCAN_B];
    int i = blockIdx.x * SCAN_B + threadIdx.x;
    int v = (i < N_NODES) ? g_cnt[i] : 0;
    sm[threadIdx.x] = v;
    __syncthreads();
    #pragma unroll
    for (int off = 1; off < SCAN_B; off <<= 1) {
        int t = (threadIdx.x >= off) ? sm[threadIdx.x - off] : 0;
        __syncthreads();
        sm[threadIdx.x] += t;
        __syncthreads();
    }
    if (i < N_NODES) g_excl[i] = sm[threadIdx.x] - v;
    if (threadIdx.x == SCAN_B - 1) g_bsum[blockIdx.x] = sm[SCAN_B - 1];
}

// ---------------- K2b: parallel exclusive scan of block sums ----------------
__global__ void k_scan2() {
    __shared__ int sm[128];
    int t = threadIdx.x;
    int v = (t < NSCAN_BLKS) ? g_bsum[t] : 0;
    sm[t] = v;
    __syncthreads();
    #pragma unroll
    for (int off = 1; off < 128; off <<= 1) {
        int u = (t >= off) ? sm[t - off] : 0;
        __syncthreads();
        sm[t] += u;
        __syncthreads();
    }
    if (t < NSCAN_BLKS) g_boff[t] = sm[t] - v;
}

// ---------------- K2c: rowptr, cursors, dinv ----------------
__global__ void k_scan3() {
    int i = blockIdx.x * blockDim.x + threadIdx.x;
    if (i >= N_NODES) return;
    int base = g_excl[i] + g_boff[i >> 10];
    g_rowptr[i] = base;
    g_cursor[i] = base;
    g_dinv[i]   = rsqrtf((float)g_cnt[i] + 1.0f);
}

// ---------------- K3: fill CSR ----------------
__global__ void k_fill(const int* __restrict__ src, const int* __restrict__ dst) {
    int e = blockIdx.x * blockDim.x + threadIdx.x;
    if (e >= N_EDGES) return;
    int pos = atomicAdd(&g_cursor[dst[e]], 1);
    g_esrc[pos] = src[e];
}

// ---------------- K4: h1 = x@W1 (fp16 out) ; insize ------------------------
__global__ void k_layer1(const float* __restrict__ x, const float* __restrict__ W1) {
    __shared__ float w[IN_F * HDIM];
    __shared__ float xs[16 * IN_F];
    int j = threadIdx.x;
    #pragma unroll
    for (int k = j; k < IN_F * HDIM; k += HDIM) w[k] = W1[k];
    int base = blockIdx.x * 16;
    for (int k = j; k < 16 * IN_F; k += HDIM) xs[k] = x[(size_t)base * IN_F + k];
    __syncthreads();

    __half* hh = (__half*)g_hh;
    #pragma unroll
    for (int t = 0; t < 16; t++) {
        int i = base + t;
        float h = xs[t*4+0] * w[0*HDIM + j]
                + xs[t*4+1] * w[1*HDIM + j]
                + xs[t*4+2] * w[2*HDIM + j]
                + xs[t*4+3] * w[3*HDIM + j];
        hh[(size_t)i*HDIM + j] = __float2half(h);
        if (j == 0 && xs[t*4+0] != 0.0f && xs[t*4+1] != 0.0f) atomicAdd(&g_insize, 1);
    }
}

// ---------------- K5/K7: gather aggregation (warp per dst node) ------------
template<int DIR>
__global__ void k_gather() {
    int node = (blockIdx.x * blockDim.x + threadIdx.x) >> 5;
    int lane = threadIdx.x & 31;
    if (node >= N_NODES) return;
    int   start = g_rowptr[node];
    int   cnt   = g_cnt[node];
    float dvd   = g_dinv[node];

    const uint2* hv = (const uint2*)g_hh;

    uint2 u = hv[(size_t)node * 32 + lane];
    __half2 p0 = *reinterpret_cast<__half2*>(&u.x);
    __half2 p1 = *reinterpret_cast<__half2*>(&u.y);
    float2 f0 = __half22float2(p0);
    float2 f1 = __half22float2(p1);
    float s2 = dvd * dvd;
    float4 acc = make_float4(f0.x * s2, f0.y * s2, f1.x * s2, f1.y * s2);

    for (int k = 0; k < cnt; k++) {
        int   s  = __ldg(&g_esrc[start + k]);
        float nr = g_dinv[s] * dvd;
        uint2 v = hv[(size_t)s * 32 + lane];
        __half2 q0 = *reinterpret_cast<__half2*>(&v.x);
        __half2 q1 = *reinterpret_cast<__half2*>(&v.y);
        float2 g0 = __half22float2(q0);
        float2 g1 = __half22float2(q1);
        acc.x += g0.x * nr; acc.y += g0.y * nr;
        acc.z += g1.x * nr; acc.w += g1.y * nr;
    }
    ((float4*)g_agg)[(size_t)node * 32 + lane] = acc;
}

// ---------------- K6: t = tanh(agg+b1); h2 = t@W2 (FFMA2, fp16 out) --------
// 64 nodes x 128 cols per block, 256 threads, 4x8 tile, k packed in pairs.
__global__ void k_layer2(const float* __restrict__ b1) {
    __shared__ float ts[64][HDIM];     // 32 KB
    int tid  = threadIdx.x;
    int base = blockIdx.x * 64;

    for (int idx = tid; idx < 64 * HDIM; idx += 256) {
        int t = idx >> 7, c = idx & 127;
        int node = base + t;
        ts[t][c] = (node < N_NODES) ? tanhf(g_agg[(size_t)node*HDIM + c] + b1[c]) : 0.0f;
    }
    __syncthreads();

    int a = tid >> 4;          // 0..15 : node group (4 nodes)
    int b = tid & 15;          // 0..15 : col group  (8 cols)

    unsigned long long acc2[4][8];     // each holds {even-k partial, odd-k partial}
    #pragma unroll
    for (int i = 0; i < 4; i++)
        #pragma unroll
        for (int j = 0; j < 8; j++) acc2[i][j] = 0ULL;

    const float* wpb = &g_wp[b * 16];
    #pragma unroll 2
    for (int kk = 0; kk < 64; kk++) {
        unsigned long long av[4];
        #pragma unroll
        for (int i = 0; i < 4; i++) av[i] = ld_u64(&ts[a*4+i][kk*2]);  // LDS.64

        const float* wrow = wpb + kk * 256;
        unsigned long long wv[8];
        #pragma unroll
        for (int j = 0; j < 8; j += 2) {
            uint4 q = *(const uint4*)(wrow + j*2);          // LDG.128: pairs j, j+1
            wv[j]   = (unsigned long long)q.x | ((unsigned long long)q.y << 32);
            wv[j+1] = (unsigned long long)q.z | ((unsigned long long)q.w << 32);
        }
        #pragma unroll
        for (int j = 0; j < 8; j++) {
            fma2(acc2[0][j], av[0], wv[j]);
            fma2(acc2[1][j], av[1], wv[j]);
            fma2(acc2[2][j], av[2], wv[j]);
            fma2(acc2[3][j], av[3], wv[j]);
        }
    }

    __half* hh = (__half*)g_hh;
    #pragma unroll
    for (int i = 0; i < 4; i++) {
        int node = base + a*4 + i;
        if (node < N_NODES) {
            float r[8];
            #pragma unroll
            for (int j = 0; j < 8; j++) {
                float lo = __uint_as_float((unsigned)(acc2[i][j] & 0xFFFFFFFFu));
                float hi = __uint_as_float((unsigned)(acc2[i][j] >> 32));
                r[j] = lo + hi;
            }
            __half2 h2v[4];
            #pragma unroll
            for (int j = 0; j < 4; j++)
                h2v[j] = __floats2half2_rn(r[2*j], r[2*j+1]);
            *(uint4*)&hh[(size_t)node*HDIM + b*8] = *(uint4*)h2v;
        }
    }
}

// ---------------- K8: h = tanh(agg+b2); column-sum pooling ----------------
__global__ void k_pool(const float* __restrict__ b2) {
    int j = threadIdx.x;
    float bj = b2[j];
    float part = 0.0f;
    for (int i = blockIdx.x; i < N_NODES; i += gridDim.x)
        part += tanhf(g_agg[(size_t)i*HDIM + j] + bj);
    atomicAdd(&g_sums[j], part);
}

// ---------------- K9: pooled mean, FC, mask -------------------------------
__global__ void k_out(const float* __restrict__ Wfc, const float* __restrict__ bfc,
                      float* __restrict__ out) {
    __shared__ float pooled[HDIM];
    int t = threadIdx.x;
    pooled[t] = g_sums[t] * (1.0f / (float)N_NODES);
    __syncthreads();
    if (t < R_ROB * OUT_F) {
        float acc = bfc[t];
        #pragma unroll 8
        for (int k = 0; k < HDIM; k++)
            acc += pooled[k] * Wfc[k * (R_ROB * OUT_F) + t];
        int r = t / OUT_F;
        out[t] = (r < g_insize) ? acc : 0.0f;
    }
}

// ---------------- launch ----------------
extern "C" void kernel_launch(void* const* d_in, const int* in_sizes, int n_in,
                              void* d_out, int out_size) {
    const float* x   = (const float*)d_in[0];
    const int*   ei  = (const int*)  d_in[1];
    const float* W1  = (const float*)d_in[3];
    const float* b1  = (const float*)d_in[4];
    const float* W2  = (const float*)d_in[5];
    const float* b2  = (const float*)d_in[6];
    const float* Wfc = (const float*)d_in[7];
    const float* bfc = (const float*)d_in[8];
    float* out = (float*)d_out;

    const int* src = ei;
    const int* dst = ei + N_EDGES;

    k_init <<<(N_NODES + 255) / 256, 256>>>();
    k_prepW<<<32, 256>>>(W2);
    k_count<<<(N_EDGES + 255) / 256, 256>>>(dst);
    k_scan1<<<NSCAN_BLKS, SCAN_B>>>();
    k_scan2<<<1, 128>>>();
    k_scan3<<<(N_NODES + 255) / 256, 256>>>();
    k_fill <<<(N_EDGES + 255) / 256, 256>>>(src, dst);

    k_layer1<<<N_NODES / 16, 128>>>(x, W1);

    int gthr_blocks = (N_NODES * 32 + 255) / 256;          // warp per node
    k_gather<0><<<gthr_blocks, 256>>>();

    k_layer2<<<(N_NODES + 63) / 64, 256>>>(b1);

    k_gather<1><<<gthr_blocks, 256>>>();

    k_pool<<<592, 128>>>(b2);
    k_out <<<1, 128>>>(Wfc, bfc, out);
}

// round 6
// speedup vs baseline: 1.6330x; 1.6330x over previous
#include <cuda_runtime.h>
#include <cuda_bf16.h>
#include <cuda_fp16.h>
#include <cstdint>

#define N_NODES 100000
#define N_EDGES 1600000
#define IN_F    4
#define HDIM    128
#define R_ROB   20
#define OUT_F   2

#define SCAN_B      1024
#define NSCAN_BLKS  ((N_NODES + SCAN_B - 1) / SCAN_B)   // 98

// ---------------- scratch (device globals; no allocation allowed) ----------
__device__ __half2 g_hh [(size_t)N_NODES * HDIM / 2];  // fp16 PRE-SCALED features (h*dinv)
__device__ float   g_agg[(size_t)N_NODES * HDIM];      // aggregation result (fp32)
__device__ float   g_dinv[N_NODES];
__device__ float   g_sums[HDIM];
__device__ int     g_insize;

__device__ int g_cnt   [N_NODES];
__device__ int g_excl  [N_NODES];
__device__ int g_rowptr[N_NODES];
__device__ int g_cursor[N_NODES];
__device__ int g_bsum  [NSCAN_BLKS];
__device__ int g_boff  [NSCAN_BLKS];
__device__ int g_esrc  [N_EDGES];

// ---------------- K0: init ----------------
__global__ void k_init() {
    int i = blockIdx.x * blockDim.x + threadIdx.x;
    if (i < N_NODES) g_cnt[i] = 0;
    if (i < HDIM)    g_sums[i] = 0.0f;
    if (i == 0)      g_insize = 0;
}

// ---------------- K1: count in-degree ----------------
__global__ void k_count(const int* __restrict__ dst) {
    int e = blockIdx.x * blockDim.x + threadIdx.x;
    if (e < N_EDGES) atomicAdd(&g_cnt[dst[e]], 1);
}

// ---------------- K2a: per-block inclusive scan ----------------
__global__ void k_scan1() {
    __shared__ int sm[SCAN_B];
    int i = blockIdx.x * SCAN_B + threadIdx.x;
    int v = (i < N_NODES) ? g_cnt[i] : 0;
    sm[threadIdx.x] = v;
    __syncthreads();
    #pragma unroll
    for (int off = 1; off < SCAN_B; off <<= 1) {
        int t = (threadIdx.x >= off) ? sm[threadIdx.x - off] : 0;
        __syncthreads();
        sm[threadIdx.x] += t;
        __syncthreads();
    }
    if (i < N_NODES) g_excl[i] = sm[threadIdx.x] - v;
    if (threadIdx.x == SCAN_B - 1) g_bsum[blockIdx.x] = sm[SCAN_B - 1];
}

// ---------------- K2b: parallel exclusive scan of block sums ---------------
__global__ void k_scan2() {
    __shared__ int sm[128];
    int t = threadIdx.x;
    int v = (t < NSCAN_BLKS) ? g_bsum[t] : 0;
    sm[t] = v;
    __syncthreads();
    #pragma unroll
    for (int off = 1; off < 128; off <<= 1) {
        int u = (t >= off) ? sm[t - off] : 0;
        __syncthreads();
        sm[t] += u;
        __syncthreads();
    }
    if (t < NSCAN_BLKS) g_boff[t] = sm[t] - v;
}

// ---------------- K2c: rowptr, cursors, dinv ----------------
__global__ void k_scan3() {
    int i = blockIdx.x * blockDim.x + threadIdx.x;
    if (i >= N_NODES) return;
    int base = g_excl[i] + g_boff[i >> 10];
    g_rowptr[i] = base;
    g_cursor[i] = base;
    g_dinv[i]   = rsqrtf((float)g_cnt[i] + 1.0f);   // +1 self-loop
}

// ---------------- K3: fill CSR ----------------
__global__ void k_fill(const int* __restrict__ src, const int* __restrict__ dst) {
    int e = blockIdx.x * blockDim.x + threadIdx.x;
    if (e >= N_EDGES) return;
    int pos = atomicAdd(&g_cursor[dst[e]], 1);
    g_esrc[pos] = src[e];
}

// ---------------- K4: hh = (x@W1)*dinv (fp16) ; insize ---------------------
// Must run AFTER k_scan3 (needs g_dinv).
__global__ void k_layer1(const float* __restrict__ x, const float* __restrict__ W1) {
    __shared__ float w[IN_F * HDIM];
    __shared__ float xs[16 * IN_F];
    int j = threadIdx.x;
    #pragma unroll
    for (int k = j; k < IN_F * HDIM; k += HDIM) w[k] = W1[k];
    int base = blockIdx.x * 16;
    for (int k = j; k < 16 * IN_F; k += HDIM) xs[k] = x[(size_t)base * IN_F + k];
    __syncthreads();

    __half* hh = (__half*)g_hh;
    #pragma unroll
    for (int t = 0; t < 16; t++) {
        int i = base + t;
        float h = xs[t*4+0] * w[0*HDIM + j]
                + xs[t*4+1] * w[1*HDIM + j]
                + xs[t*4+2] * w[2*HDIM + j]
                + xs[t*4+3] * w[3*HDIM + j];
        hh[(size_t)i*HDIM + j] = __float2half(h * g_dinv[i]);
        if (j == 0 && xs[t*4+0] != 0.0f && xs[t*4+1] != 0.0f) atomicAdd(&g_insize, 1);
    }
}

// ---------------- K5/K7: gather aggregation (warp per dst node) ------------
// agg[d] = dinv[d] * ( hh[d] + sum_s hh[s] )      (hh is pre-scaled by dinv)
template<int DIR>
__global__ void k_gather() {
    int node = (blockIdx.x * blockDim.x + threadIdx.x) >> 5;
    int lane = threadIdx.x & 31;
    if (node >= N_NODES) return;
    int   start = g_rowptr[node];
    int   cnt   = g_cnt[node];
    float dvd   = g_dinv[node];

    const uint2* hv = (const uint2*)g_hh;   // 8B = 4 halfs per lane

    uint2 u = hv[(size_t)node * 32 + lane];
    __half2 p0 = *reinterpret_cast<__half2*>(&u.x);
    __half2 p1 = *reinterpret_cast<__half2*>(&u.y);
    float2 f0 = __half22float2(p0);
    float2 f1 = __half22float2(p1);
    float4 acc = make_float4(f0.x, f0.y, f1.x, f1.y);   // self-loop term

    for (int bat = 0; bat < cnt; bat += 32) {
        int idx = start + bat + lane;
        int sv  = (bat + lane < cnt) ? __ldg(&g_esrc[idx]) : 0;
        int m   = min(32, cnt - bat);
        for (int t = 0; t < m; t++) {
            int s = __shfl_sync(0xffffffffu, sv, t);
            uint2 v = hv[(size_t)s * 32 + lane];
            __half2 q0 = *reinterpret_cast<__half2*>(&v.x);
            __half2 q1 = *reinterpret_cast<__half2*>(&v.y);
            float2 g0 = __half22float2(q0);
            float2 g1 = __half22float2(q1);
            acc.x += g0.x; acc.y += g0.y;
            acc.z += g1.x; acc.w += g1.y;
        }
    }
    acc.x *= dvd; acc.y *= dvd; acc.z *= dvd; acc.w *= dvd;
    ((float4*)g_agg)[(size_t)node * 32 + lane] = acc;
}

// ---------------- K6: t = tanh(agg+b1); hh = (t@W2)*dinv (fp16) ------------
// 64 nodes x 128 cols per block, 256 threads, 4x8 register tile per thread.
__global__ void k_layer2(const float* __restrict__ b1, const float* __restrict__ W2) {
    __shared__ float ts[64][HDIM];     // 32 KB
    int tid  = threadIdx.x;
    int base = blockIdx.x * 64;

    for (int idx = tid; idx < 64 * HDIM; idx += 256) {
        int t = idx >> 7, c = idx & 127;
        int node = base + t;
        ts[t][c] = (node < N_NODES) ? tanhf(g_agg[(size_t)node*HDIM + c] + b1[c]) : 0.0f;
    }
    __syncthreads();

    int a = tid >> 4;          // 0..15 : node group (4 nodes)
    int b = tid & 15;          // 0..15 : col group  (8 cols)

    float acc[4][8];
    #pragma unroll
    for (int i = 0; i < 4; i++)
        #pragma unroll
        for (int j = 0; j < 8; j++) acc[i][j] = 0.0f;

    #pragma unroll 4
    for (int k = 0; k < HDIM; k++) {
        float a0 = ts[a*4+0][k], a1 = ts[a*4+1][k];
        float a2 = ts[a*4+2][k], a3 = ts[a*4+3][k];
        float4 w0 = *(const float4*)&W2[k*HDIM + b*8];      // L1-resident (64KB)
        float4 w1 = *(const float4*)&W2[k*HDIM + b*8 + 4];
        float wv[8] = {w0.x,w0.y,w0.z,w0.w,w1.x,w1.y,w1.z,w1.w};
        #pragma unroll
        for (int j = 0; j < 8; j++) {
            acc[0][j] += a0 * wv[j];
            acc[1][j] += a1 * wv[j];
            acc[2][j] += a2 * wv[j];
            acc[3][j] += a3 * wv[j];
        }
    }

    __half* hh = (__half*)g_hh;
    #pragma unroll
    for (int i = 0; i < 4; i++) {
        int node = base + a*4 + i;
        if (node < N_NODES) {
            float dv = g_dinv[node];
            __half2 h2v[4];
            #pragma unroll
            for (int j = 0; j < 4; j++)
                h2v[j] = __floats2half2_rn(acc[i][2*j] * dv, acc[i][2*j+1] * dv);
            *(uint4*)&hh[(size_t)node*HDIM + b*8] = *(uint4*)h2v;  // 16B store
        }
    }
}

// ---------------- K8: h = tanh(agg+b2); column-sum pooling ----------------
__global__ void k_pool(const float* __restrict__ b2) {
    int j = threadIdx.x;
    float bj = b2[j];
    float part = 0.0f;
    for (int i = blockIdx.x; i < N_NODES; i += gridDim.x)
        part += tanhf(g_agg[(size_t)i*HDIM + j] + bj);
    atomicAdd(&g_sums[j], part);
}

// ---------------- K9: pooled mean, FC, mask -------------------------------
__global__ void k_out(const float* __restrict__ Wfc, const float* __restrict__ bfc,
                      float* __restrict__ out) {
    __shared__ float pooled[HDIM];
    int t = threadIdx.x;
    pooled[t] = g_sums[t] * (1.0f / (float)N_NODES);
    __syncthreads();
    if (t < R_ROB * OUT_F) {
        float acc = bfc[t];
        #pragma unroll 8
        for (int k = 0; k < HDIM; k++)
            acc += pooled[k] * Wfc[k * (R_ROB * OUT_F) + t];
        int r = t / OUT_F;
        out[t] = (r < g_insize) ? acc : 0.0f;
    }
}

// ---------------- launch ----------------
extern "C" void kernel_launch(void* const* d_in, const int* in_sizes, int n_in,
                              void* d_out, int out_size) {
    const float* x   = (const float*)d_in[0];
    const int*   ei  = (const int*)  d_in[1];
    const float* W1  = (const float*)d_in[3];
    const float* b1  = (const float*)d_in[4];
    const float* W2  = (const float*)d_in[5];
    const float* b2  = (const float*)d_in[6];
    const float* Wfc = (const float*)d_in[7];
    const float* bfc = (const float*)d_in[8];
    float* out = (float*)d_out;

    const int* src = ei;
    const int* dst = ei + N_EDGES;

    k_init <<<(N_NODES + 255) / 256, 256>>>();
    k_count<<<(N_EDGES + 255) / 256, 256>>>(dst);
    k_scan1<<<NSCAN_BLKS, SCAN_B>>>();
    k_scan2<<<1, 128>>>();
    k_scan3<<<(N_NODES + 255) / 256, 256>>>();
    k_fill <<<(N_EDGES + 255) / 256, 256>>>(src, dst);

    k_layer1<<<N_NODES / 16, 128>>>(x, W1);     // after scan3: needs dinv

    int gthr_blocks = (N_NODES * 32 + 255) / 256;          // warp per node
    k_gather<0><<<gthr_blocks, 256>>>();

    k_layer2<<<(N_NODES + 63) / 64, 256>>>(b1, W2);

    k_gather<1><<<gthr_blocks, 256>>>();

    k_pool<<<592, 128>>>(b2);
    k_out <<<1, 128>>>(Wfc, bfc, out);
}

// round 7
// speedup vs baseline: 1.8885x; 1.1565x over previous
#include <cuda_runtime.h>
#include <cuda_bf16.h>
#include <cuda_fp16.h>
#include <cstdint>

#define N_NODES 100000
#define N_EDGES 1600000
#define IN_F    4
#define HDIM    128
#define R_ROB   20
#define OUT_F   2

#define SCAN_B      1024
#define NSCAN_BLKS  ((N_NODES + SCAN_B - 1) / SCAN_B)   // 98

// ---------------- scratch (device globals; no allocation allowed) ----------
__device__ __half2 g_hh[(size_t)N_NODES * HDIM / 2];  // fp16 pre-scaled features h*dinv
__device__ __half2 g_t [(size_t)N_NODES * HDIM / 2];  // fp16 tanh(agg1+b1)
__device__ float   g_dinv[N_NODES];
__device__ float   g_sums_s[HDIM * 32];                // strided col sums (1 line apart)
__device__ int     g_insize;

__device__ int g_cnt   [N_NODES];
__device__ int g_excl  [N_NODES];
__device__ int g_rowptr[N_NODES];
__device__ int g_cursor[N_NODES];
__device__ int g_bsum  [NSCAN_BLKS];
__device__ int g_boff  [NSCAN_BLKS];
__device__ int g_esrc  [N_EDGES];

// ---------------- K0: init ----------------
__global__ void k_init() {
    int i = blockIdx.x * blockDim.x + threadIdx.x;
    if (i < N_NODES)   g_cnt[i] = 0;
    if (i < HDIM * 32) g_sums_s[i] = 0.0f;
    if (i == 0)        g_insize = 0;
}

// ---------------- K1: count in-degree ----------------
__global__ void k_count(const int* __restrict__ dst) {
    int e = blockIdx.x * blockDim.x + threadIdx.x;
    if (e < N_EDGES) atomicAdd(&g_cnt[dst[e]], 1);
}

// ---------------- K2a: per-block inclusive scan ----------------
__global__ void k_scan1() {
    __shared__ int sm[SCAN_B];
    int i = blockIdx.x * SCAN_B + threadIdx.x;
    int v = (i < N_NODES) ? g_cnt[i] : 0;
    sm[threadIdx.x] = v;
    __syncthreads();
    #pragma unroll
    for (int off = 1; off < SCAN_B; off <<= 1) {
        int t = (threadIdx.x >= off) ? sm[threadIdx.x - off] : 0;
        __syncthreads();
        sm[threadIdx.x] += t;
        __syncthreads();
    }
    if (i < N_NODES) g_excl[i] = sm[threadIdx.x] - v;
    if (threadIdx.x == SCAN_B - 1) g_bsum[blockIdx.x] = sm[SCAN_B - 1];
}

// ---------------- K2b: parallel exclusive scan of block sums ---------------
__global__ void k_scan2() {
    __shared__ int sm[128];
    int t = threadIdx.x;
    int v = (t < NSCAN_BLKS) ? g_bsum[t] : 0;
    sm[t] = v;
    __syncthreads();
    #pragma unroll
    for (int off = 1; off < 128; off <<= 1) {
        int u = (t >= off) ? sm[t - off] : 0;
        __syncthreads();
        sm[t] += u;
        __syncthreads();
    }
    if (t < NSCAN_BLKS) g_boff[t] = sm[t] - v;
}

// ---------------- K2c: rowptr, cursors, dinv ----------------
__global__ void k_scan3() {
    int i = blockIdx.x * blockDim.x + threadIdx.x;
    if (i >= N_NODES) return;
    int base = g_excl[i] + g_boff[i >> 10];
    g_rowptr[i] = base;
    g_cursor[i] = base;
    g_dinv[i]   = rsqrtf((float)g_cnt[i] + 1.0f);   // +1 self-loop
}

// ---------------- K3: fill CSR ----------------
__global__ void k_fill(const int* __restrict__ src, const int* __restrict__ dst) {
    int e = blockIdx.x * blockDim.x + threadIdx.x;
    if (e >= N_EDGES) return;
    int pos = atomicAdd(&g_cursor[dst[e]], 1);
    g_esrc[pos] = src[e];
}

// ---------------- K4: hh = (x@W1)*dinv (fp16) ; insize ---------------------
__global__ void k_layer1(const float* __restrict__ x, const float* __restrict__ W1) {
    __shared__ float w[IN_F * HDIM];
    __shared__ float xs[16 * IN_F];
    int j = threadIdx.x;
    #pragma unroll
    for (int k = j; k < IN_F * HDIM; k += HDIM) w[k] = W1[k];
    int base = blockIdx.x * 16;
    for (int k = j; k < 16 * IN_F; k += HDIM) xs[k] = x[(size_t)base * IN_F + k];
    __syncthreads();

    __half* hh = (__half*)g_hh;
    #pragma unroll
    for (int t = 0; t < 16; t++) {
        int i = base + t;
        float h = xs[t*4+0] * w[0*HDIM + j]
                + xs[t*4+1] * w[1*HDIM + j]
                + xs[t*4+2] * w[2*HDIM + j]
                + xs[t*4+3] * w[3*HDIM + j];
        hh[(size_t)i*HDIM + j] = __float2half(h * g_dinv[i]);
        if (j == 0 && xs[t*4+0] != 0.0f && xs[t*4+1] != 0.0f) atomicAdd(&g_insize, 1);
    }
}

// ---------------- warp gather core: acc = hh[d] + sum_s hh[s] --------------
__device__ __forceinline__ float4 gather_acc(int node, int lane) {
    int start = g_rowptr[node];
    int cnt   = g_cnt[node];
    const uint2* hv = (const uint2*)g_hh;

    uint2 u = hv[(size_t)node * 32 + lane];
    __half2 p0 = *reinterpret_cast<__half2*>(&u.x);
    __half2 p1 = *reinterpret_cast<__half2*>(&u.y);
    float2 f0 = __half22float2(p0);
    float2 f1 = __half22float2(p1);
    float4 acc = make_float4(f0.x, f0.y, f1.x, f1.y);

    for (int bat = 0; bat < cnt; bat += 32) {
        int sv = (bat + lane < cnt) ? __ldg(&g_esrc[start + bat + lane]) : 0;
        int m  = min(32, cnt - bat);
        for (int t = 0; t < m; t++) {
            int s = __shfl_sync(0xffffffffu, sv, t);
            uint2 v = hv[(size_t)s * 32 + lane];
            __half2 q0 = *reinterpret_cast<__half2*>(&v.x);
            __half2 q1 = *reinterpret_cast<__half2*>(&v.y);
            float2 g0 = __half22float2(q0);
            float2 g1 = __half22float2(q1);
            acc.x += g0.x; acc.y += g0.y;
            acc.z += g1.x; acc.w += g1.y;
        }
    }
    return acc;
}

// ---------------- K5: gather #1 -> t = tanh(dinv*acc + b1) (fp16) ----------
__global__ void k_gather_t(const float* __restrict__ b1) {
    int node = (blockIdx.x * blockDim.x + threadIdx.x) >> 5;
    int lane = threadIdx.x & 31;
    if (node >= N_NODES) return;
    float dvd = g_dinv[node];
    float4 acc = gather_acc(node, lane);
    float4 bv  = *(const float4*)&b1[lane * 4];
    float t0 = tanhf(acc.x * dvd + bv.x);
    float t1 = tanhf(acc.y * dvd + bv.y);
    float t2 = tanhf(acc.z * dvd + bv.z);
    float t3 = tanhf(acc.w * dvd + bv.w);
    __half2 o[2] = { __floats2half2_rn(t0, t1), __floats2half2_rn(t2, t3) };
    ((uint2*)g_t)[(size_t)node * 32 + lane] = *(uint2*)o;
}

// ---------------- K6: load t (fp16); h2 = t@W2; hh = h2*dinv (fp16) --------
__global__ void k_layer2(const float* __restrict__ W2) {
    __shared__ float ts[64][HDIM];     // 32 KB
    int tid  = threadIdx.x;
    int base = blockIdx.x * 64;        // N_NODES divisible by 64? 100000/64 no -> guard

    const uint2* tv = (const uint2*)g_t;
    for (int idx = tid; idx < 64 * 32; idx += 256) {   // 64 rows x 32 uint2
        int t = idx >> 5, c = idx & 31;
        int node = base + t;
        float4 f;
        if (node < N_NODES) {
            uint2 v = tv[(size_t)node * 32 + c];
            __half2 q0 = *reinterpret_cast<__half2*>(&v.x);
            __half2 q1 = *reinterpret_cast<__half2*>(&v.y);
            float2 g0 = __half22float2(q0);
            float2 g1 = __half22float2(q1);
            f = make_float4(g0.x, g0.y, g1.x, g1.y);
        } else f = make_float4(0.f, 0.f, 0.f, 0.f);
        *(float4*)&ts[t][c * 4] = f;
    }
    __syncthreads();

    int a = tid >> 4;          // 0..15 : node group (4 nodes)
    int b = tid & 15;          // 0..15 : col group  (8 cols)

    float acc[4][8];
    #pragma unroll
    for (int i = 0; i < 4; i++)
        #pragma unroll
        for (int j = 0; j < 8; j++) acc[i][j] = 0.0f;

    #pragma unroll 4
    for (int k = 0; k < HDIM; k++) {
        float a0 = ts[a*4+0][k], a1 = ts[a*4+1][k];
        float a2 = ts[a*4+2][k], a3 = ts[a*4+3][k];
        float4 w0 = *(const float4*)&W2[k*HDIM + b*8];      // L1-resident (64KB)
        float4 w1 = *(const float4*)&W2[k*HDIM + b*8 + 4];
        float wv[8] = {w0.x,w0.y,w0.z,w0.w,w1.x,w1.y,w1.z,w1.w};
        #pragma unroll
        for (int j = 0; j < 8; j++) {
            acc[0][j] += a0 * wv[j];
            acc[1][j] += a1 * wv[j];
            acc[2][j] += a2 * wv[j];
            acc[3][j] += a3 * wv[j];
        }
    }

    __half* hh = (__half*)g_hh;
    #pragma unroll
    for (int i = 0; i < 4; i++) {
        int node = base + a*4 + i;
        if (node < N_NODES) {
            float dv = g_dinv[node];
            __half2 h2v[4];
            #pragma unroll
            for (int j = 0; j < 4; j++)
                h2v[j] = __floats2half2_rn(acc[i][2*j] * dv, acc[i][2*j+1] * dv);
            *(uint4*)&hh[(size_t)node*HDIM + b*8] = *(uint4*)h2v;
        }
    }
}

// ---------------- K7: gather #2 + tanh + mean-pool (fused) ----------------
// 8 warps/block = 8 nodes/block; smem column accumulators; strided global adds.
__global__ void k_gather_pool(const float* __restrict__ b2) {
    __shared__ float ssum[HDIM];
    int tid  = threadIdx.x;
    int node = (blockIdx.x * blockDim.x + tid) >> 5;
    int lane = tid & 31;
    if (tid < HDIM) ssum[tid] = 0.0f;
    __syncthreads();

    if (node < N_NODES) {
        float dvd = g_dinv[node];
        float4 acc = gather_acc(node, lane);
        float4 bv  = *(const float4*)&b2[lane * 4];
        atomicAdd(&ssum[lane*4+0], tanhf(acc.x * dvd + bv.x));
        atomicAdd(&ssum[lane*4+1], tanhf(acc.y * dvd + bv.y));
        atomicAdd(&ssum[lane*4+2], tanhf(acc.z * dvd + bv.z));
        atomicAdd(&ssum[lane*4+3], tanhf(acc.w * dvd + bv.w));
    }
    __syncthreads();
    if (tid < HDIM) atomicAdd(&g_sums_s[tid * 32], ssum[tid]);
}

// ---------------- K8: pooled mean, FC, mask -------------------------------
__global__ void k_out(const float* __restrict__ Wfc, const float* __restrict__ bfc,
                      float* __restrict__ out) {
    __shared__ float pooled[HDIM];
    int t = threadIdx.x;
    pooled[t] = g_sums_s[t * 32] * (1.0f / (float)N_NODES);
    __syncthreads();
    if (t < R_ROB * OUT_F) {
        float acc = bfc[t];
        #pragma unroll 8
        for (int k = 0; k < HDIM; k++)
            acc += pooled[k] * Wfc[k * (R_ROB * OUT_F) + t];
        int r = t / OUT_F;
        out[t] = (r < g_insize) ? acc : 0.0f;
    }
}

// ---------------- launch ----------------
extern "C" void kernel_launch(void* const* d_in, const int* in_sizes, int n_in,
                              void* d_out, int out_size) {
    const float* x   = (const float*)d_in[0];
    const int*   ei  = (const int*)  d_in[1];
    const float* W1  = (const float*)d_in[3];
    const float* b1  = (const float*)d_in[4];
    const float* W2  = (const float*)d_in[5];
    const float* b2  = (const float*)d_in[6];
    const float* Wfc = (const float*)d_in[7];
    const float* bfc = (const float*)d_in[8];
    float* out = (float*)d_out;

    const int* src = ei;
    const int* dst = ei + N_EDGES;

    k_init <<<(N_NODES + 255) / 256, 256>>>();
    k_count<<<(N_EDGES + 255) / 256, 256>>>(dst);
    k_scan1<<<NSCAN_BLKS, SCAN_B>>>();
    k_scan2<<<1, 128>>>();
    k_scan3<<<(N_NODES + 255) / 256, 256>>>();
    k_fill <<<(N_EDGES + 255) / 256, 256>>>(src, dst);

    k_layer1<<<N_NODES / 16, 128>>>(x, W1);     // after scan3: needs dinv

    int gthr_blocks = (N_NODES * 32 + 255) / 256;   // warp per node
    k_gather_t<<<gthr_blocks, 256>>>(b1);

    k_layer2<<<(N_NODES + 63) / 64, 256>>>(W2);

    k_gather_pool<<<gthr_blocks, 256>>>(b2);

    k_out<<<1, 128>>>(Wfc, bfc, out);
}